// round 17
// baseline (speedup 1.0000x reference)
#include <cuda_runtime.h>
#include <math.h>

// ---------------- problem geometry ----------------
#define LTOT 28928          // tokens per batch across seqs 0..3
#define BTOK 231424         // 8 * LTOT
#define TOTC 452            // chunks (T=64) per batch: 341+85+21+5
#define NB   8

// ---------------- static device scratch ----------------
__device__ __align__(16) float g_P[NB*TOTC*256];  // per-chunk product of a
__device__ __align__(16) float g_S[NB*TOTC*256];  // per-chunk local scan end
__device__ __align__(16) float g_H[NB*TOTC*256];  // h_start per chunk

__constant__ int c_plen[5]  = {16384,4096,1024,256,64};      // spatial size per tensor (= ch stride)
__constant__ int c_bs[5]    = {131072,65536,24576,8192,3072};// batch stride per tensor
__constant__ int c_obase[5] = {0,1048576,1572864,1769472,1835008};
__constant__ int c_O[4]     = {0,21824,27264,28608};         // seq offsets within a batch
__constant__ int c_CB[4]    = {0,341,426,447};               // chunk base per seq
__constant__ int c_NC[4]    = {341,85,21,5};                 // chunks per seq

__device__ __forceinline__ float siluf(float x){ return x * (1.0f/(1.0f+__expf(-x))); }
__device__ __forceinline__ float softplusf(float x){ return (x>20.0f)? x : log1pf(__expf(x)); }

// ======= shared record recompute (includes gather + in-proj) ==========
// BCt[t][n] = {B,C}, row stride 18 float2 = 144B (16B-aligned rows -> float4 reads)
// zsh removed: k5 epilogue recomputes z from x8h + iw.
struct alignas(16) RecSmem {
  float  xi[16][68];      // 4352 B (aliased as y after conv)
  float  xcs[16][68];     // 4352 B
  float  x8h[8][68];      // 2176 B
  float2 dldu[16][65];    // 8320 B {delta, delta*xc}
  float2 BCt[64][18];     // 9216 B {B, C} transposed
  float  dtv[64];         // 256 B
  float  xp[564];         // 33 rows, stride 17 (2256 B)
  float  iw[256];         // in_w (32,8)
  float  cw[64], cb[16], dtw[16], dtb[16];
};

template<bool WANTC>
__device__ __forceinline__ void rec_compute(RecSmem& S, int tid, int b, int s, int cis,
    const float* __restrict__ tp, int ibase, int plen,
    const float* __restrict__ t1, const float* __restrict__ t2,
    const float* __restrict__ t3, const float* __restrict__ t4,
    const float* __restrict__ t5,
    const float* __restrict__ in_w, const float* __restrict__ xproj_w,
    const float* __restrict__ conv_w, const float* __restrict__ conv_b,
    const float* __restrict__ dt_w,  const float* __restrict__ dt_b){
  for (int i=tid;i<528;i+=256){ int row=i>>4, col=i&15; S.xp[row*17+col]=xproj_w[i]; }
  S.iw[tid]=in_w[tid];
  if (tid<64) S.cw[tid]=conv_w[tid];
  if (tid<16){ S.cb[tid]=conv_b[tid]; S.dtw[tid]=dt_w[tid]; S.dtb[tid]=dt_b[tid]; }
  if (tid<128){
    int ch=tid>>4, q=tid&15;
    float4 w = *reinterpret_cast<const float4*>(&tp[ibase + ch*plen + q*4]);
    S.x8h[ch][4+q*4+0]=w.x; S.x8h[ch][4+q*4+1]=w.y;
    S.x8h[ch][4+q*4+2]=w.z; S.x8h[ch][4+q*4+3]=w.w;
  } else if (tid<160){
    int u=tid-128, j=u>>3, c=u&7;
    float v=0.f;
    if (cis>0){
      int p = cis*64 - 4 + j;
      int i2=s, pp=p;
      while (pp >= c_plen[i2]) { pp -= c_plen[i2]; ++i2; }
      const float* hp = (i2==0)?t1:(i2==1)?t2:(i2==2)?t3:(i2==3)?t4:t5;
      v = hp[b*c_bs[i2] + (8*s+c)*c_plen[i2] + pp];
    }
    S.x8h[c][j]=v;
  }
  __syncthreads();
  for (int i=tid;i<1088;i+=256){
    int d=i/68, j=i-d*68;
    float acc=0.f;
    #pragma unroll
    for (int c=0;c<8;c++) acc += S.x8h[c][j]*S.iw[d*8+c];
    S.xi[d][j]=acc;
  }
  __syncthreads();
  #pragma unroll
  for (int k=0;k<4;k++){
    int idx = tid + k*256;
    int d = idx>>6, t = idx&63;
    float acc = S.cb[d];
    #pragma unroll
    for (int kk=0;kk<4;kk++) acc += S.cw[d*4+kk]*S.xi[d][t+1+kk];
    S.xcs[d][t] = siluf(acc);
  }
  __syncthreads();
  if (tid<64){
    float v=0.f;
    #pragma unroll
    for (int d=0;d<16;d++) v += S.xcs[d][tid]*S.xp[d];
    S.dtv[tid]=v;
  }
  __syncthreads();
  {
    int j = tid & 15;
    int t0 = (tid >> 4) << 2;
    float aB0=0.f,aB1=0.f,aB2=0.f,aB3=0.f;
    float aC0=0.f,aC1=0.f,aC2=0.f,aC3=0.f;
    #pragma unroll
    for (int d=0;d<16;d++){
      float4 x4 = *reinterpret_cast<const float4*>(&S.xcs[d][t0]);
      float wb = S.xp[(1+j)*17+d];
      aB0 += x4.x*wb; aB1 += x4.y*wb; aB2 += x4.z*wb; aB3 += x4.w*wb;
      if (WANTC){
        float wc = S.xp[(17+j)*17+d];
        aC0 += x4.x*wc; aC1 += x4.y*wc; aC2 += x4.z*wc; aC3 += x4.w*wc;
      }
    }
    S.BCt[t0+0][j] = make_float2(aB0, aC0);
    S.BCt[t0+1][j] = make_float2(aB1, aC1);
    S.BCt[t0+2][j] = make_float2(aB2, aC2);
    S.BCt[t0+3][j] = make_float2(aB3, aC3);
  }
  #pragma unroll
  for (int k=0;k<4;k++){
    int idx = tid + k*256;
    int d = idx>>6, t = idx&63;
    float del = softplusf(S.dtv[t]*S.dtw[d]+S.dtb[d]);
    S.dldu[d][t] = make_float2(del, del*S.xcs[d][t]);
  }
  __syncthreads();
}

// ---------------- K3: fused gather+in-proj+record + phase A (P,S) ---------
// scan: 128 threads, thread=(d,g), h[2] in registers; P via exp2(ac * sum(delta))
__global__ void __launch_bounds__(256,6)
k3_scanA(const float* __restrict__ t1, const float* __restrict__ t2,
         const float* __restrict__ t3, const float* __restrict__ t4,
         const float* __restrict__ t5,
         const float* __restrict__ in_w, const float* __restrict__ xproj_w,
         const float* __restrict__ conv_w, const float* __restrict__ conv_b,
         const float* __restrict__ dt_w, const float* __restrict__ dt_b,
         const float* __restrict__ Alog){
  __shared__ RecSmem S;
  int blk = blockIdx.x;
  int b = blk / TOTC, cg = blk % TOTC;
  int s = (cg>=341)+(cg>=426)+(cg>=447);
  int cis = cg - c_CB[s];
  int tid = threadIdx.x;
  int ti = s, pp = cis*64;
  while (pp >= c_plen[ti]) { pp -= c_plen[ti]; ++ti; }
  const float* tp = (ti==0)?t1:(ti==1)?t2:(ti==2)?t3:(ti==3)?t4:t5;
  int ibase = b*c_bs[ti] + (8*s)*c_plen[ti] + pp;
  rec_compute<false>(S, tid, b, s, cis, tp, ibase, c_plen[ti],
                     t1,t2,t3,t4,t5, in_w, xproj_w, conv_w, conv_b, dt_w, dt_b);
  if (tid < 128){
    int d = tid>>3, g = tid&7;
    float2 al = *reinterpret_cast<const float2*>(&Alog[d*16 + 2*g]);
    const float L2E = 1.4426950408889634f;
    float ac0=-__expf(al.x)*L2E, ac1=-__expf(al.y)*L2E;
    float h0=0.f,h1=0.f, sdl=0.f;
    #pragma unroll 4
    for (int t=0;t<64;t++){
      float2 du = S.dldu[d][t];
      float4 bc = *reinterpret_cast<const float4*>(&S.BCt[t][2*g]);  // B0,C0,B1,C1
      float a0=exp2f(du.x*ac0), a1=exp2f(du.x*ac1);
      h0 = a0*h0 + du.y*bc.x;
      h1 = a1*h1 + du.y*bc.z;
      sdl += du.x;
    }
    float P0 = exp2f(sdl*ac0), P1 = exp2f(sdl*ac1);
    int idx = (b*TOTC+cg)*256 + d*16 + 2*g;
    *reinterpret_cast<float2*>(&g_P[idx]) = make_float2(P0,P1);
    *reinterpret_cast<float2*>(&g_S[idx]) = make_float2(h0,h1);
  }
}

// ---------------- K4: chunk-prefix scan, software-pipelined ----------------
__global__ void k4_chunk(){
  constexpr int U = 16;
  int b = blockIdx.x >> 2, s = blockIdx.x & 3;
  int tid = threadIdx.x;
  int base = (b*TOTC + c_CB[s])*256 + tid;
  int nc = c_NC[s];
  int nbatch = (nc + U - 1)/U;
  float PA[U],SA[U],PB[U],SB[U];
  #pragma unroll
  for (int u=0;u<U;u++){
    if (u<nc){ int idx=base+u*256; PA[u]=g_P[idx]; SA[u]=g_S[idx]; }
    else { PA[u]=1.f; SA[u]=0.f; }
  }
  float H=0.f;
  for (int bi=0; bi<nbatch; bi+=2){
    if (bi+1<nbatch){
      #pragma unroll
      for (int u=0;u<U;u++){
        int c=(bi+1)*U+u;
        if (c<nc){ int idx=base+c*256; PB[u]=g_P[idx]; SB[u]=g_S[idx]; }
        else { PB[u]=1.f; SB[u]=0.f; }
      }
    }
    #pragma unroll
    for (int u=0;u<U;u++){
      int c=bi*U+u;
      if (c<nc){ g_H[base+c*256]=H; H = PA[u]*H + SA[u]; }
    }
    if (bi+2<nbatch){
      #pragma unroll
      for (int u=0;u<U;u++){
        int c=(bi+2)*U+u;
        if (c<nc){ int idx=base+c*256; PA[u]=g_P[idx]; SA[u]=g_S[idx]; }
        else { PA[u]=1.f; SA[u]=0.f; }
      }
    }
    if (bi+1<nbatch){
      #pragma unroll
      for (int u=0;u<U;u++){
        int c=(bi+1)*U+u;
        if (c<nc){ g_H[base+c*256]=H; H = PB[u]*H + SB[u]; }
      }
    }
  }
}

// ---------------- K5: fused recompute + phase C + epilogue + scatter -------
struct alignas(16) K5Smem {
  RecSmem R;
  float ow[128], pwm[64], pbv[8], gv[8], nbvv[8], Dvv[16];
  float skip; float pad3[3];
};

__global__ void __launch_bounds__(256,6)
k5_scanC(const float* __restrict__ t1, const float* __restrict__ t2,
         const float* __restrict__ t3, const float* __restrict__ t4,
         const float* __restrict__ t5,
         const float* __restrict__ in_w, const float* __restrict__ xproj_w,
         const float* __restrict__ conv_w, const float* __restrict__ conv_b,
         const float* __restrict__ dt_w, const float* __restrict__ dt_b,
         const float* __restrict__ Alog,
         const float* __restrict__ out_w, const float* __restrict__ Dv,
         const float* __restrict__ ng_, const float* __restrict__ nbv,
         const float* __restrict__ pw, const float* __restrict__ pb,
         const float* __restrict__ skipp, float* __restrict__ out){
  __shared__ K5Smem S;
  int blk = blockIdx.x;
  int b = blk / TOTC, cg = blk % TOTC;
  int s = (cg>=341)+(cg>=426)+(cg>=447);
  int cis = cg - c_CB[s];
  int tid = threadIdx.x;
  int ti = s, pp = cis*64;
  while (pp >= c_plen[ti]) { pp -= c_plen[ti]; ++ti; }
  const float* tp = (ti==0)?t1:(ti==1)?t2:(ti==2)?t3:(ti==3)?t4:t5;
  int ibase = b*c_bs[ti] + (8*s)*c_plen[ti] + pp;
  if (tid<128) S.ow[tid]=out_w[tid];
  else {
    int u = tid-128;
    if (u<64) S.pwm[u]=pw[u];
    else if (u<72) S.pbv[u-64]=pb[u-64];
    else if (u<80) S.gv[u-72]=ng_[u-72];
    else if (u<88) S.nbvv[u-80]=nbv[u-80];
    else if (u<104) S.Dvv[u-88]=Dv[u-88];
    else if (u==104) S.skip = skipp[0];
  }
  rec_compute<true>(S.R, tid, b, s, cis, tp, ibase, c_plen[ti],
                    t1,t2,t3,t4,t5, in_w, xproj_w, conv_w, conv_b, dt_w, dt_b);
  float (*ysh)[68] = reinterpret_cast<float (*)[68]>(S.R.xi);  // xi dead after conv
  if (tid < 128){
    int d = tid>>3, g = tid&7;
    float2 al = *reinterpret_cast<const float2*>(&Alog[d*16 + 2*g]);
    const float L2E = 1.4426950408889634f;
    float ac0=-__expf(al.x)*L2E, ac1=-__expf(al.y)*L2E;
    int hidx = (b*TOTC+cg)*256 + d*16 + 2*g;
    float2 h2 = *reinterpret_cast<const float2*>(&g_H[hidx]);
    float h0=h2.x, h1=h2.y;
    #pragma unroll 4
    for (int t=0;t<64;t++){
      float2 du = S.R.dldu[d][t];
      float4 bc = *reinterpret_cast<const float4*>(&S.R.BCt[t][2*g]); // B0,C0,B1,C1
      float a0=exp2f(du.x*ac0), a1=exp2f(du.x*ac1);
      h0 = a0*h0 + du.y*bc.x;
      h1 = a1*h1 + du.y*bc.z;
      float pr = h0*bc.y + h1*bc.w;
      pr += __shfl_xor_sync(0xffffffffu, pr, 1);
      pr += __shfl_xor_sync(0xffffffffu, pr, 2);
      pr += __shfl_xor_sync(0xffffffffu, pr, 4);
      if (g==0) ysh[d][t]=pr;
    }
  }
  __syncthreads();
  // ---- epilogue on 256 threads: thread=(t, quarter q), q covers dd=q*4..q*4+3
  {
    int t = tid>>2, q = tid&3;
    float yf[4];
    #pragma unroll
    for (int i=0;i<4;i++){
      int dd = q*4+i;
      float z=0.f;        // recompute z = in-proj rows 16..31 from staged x8h
      #pragma unroll
      for (int c=0;c<8;c++) z += S.R.x8h[c][t+4]*S.R.iw[(16+dd)*8+c];
      yf[i] = (ysh[dd][t] + S.R.xcs[dd][t]*S.Dvv[dd]) * siluf(z);
    }
    float o[8];
    #pragma unroll
    for (int ch=0;ch<8;ch++){
      float4 w4 = *reinterpret_cast<const float4*>(&S.ow[ch*16+q*4]);
      float acc = yf[0]*w4.x + yf[1]*w4.y + yf[2]*w4.z + yf[3]*w4.w;
      acc += __shfl_xor_sync(0xffffffffu, acc, 1);
      acc += __shfl_xor_sync(0xffffffffu, acc, 2);
      o[ch] = acc;
    }
    if (q==0){
      float mu=0.f;
      #pragma unroll
      for (int ch=0;ch<8;ch++){ o[ch] += S.skip * S.R.x8h[ch][t+4]; mu += o[ch]; }
      mu *= 0.125f;
      float var=0.f;
      #pragma unroll
      for (int ch=0;ch<8;ch++){ float dv=o[ch]-mu; var += dv*dv; }
      var *= 0.125f;
      float rs = rsqrtf(var + 1e-5f);
      float ln[8];
      #pragma unroll
      for (int ch=0;ch<8;ch++) ln[ch] = (o[ch]-mu)*rs*S.gv[ch] + S.nbvv[ch];
      int base = c_obase[ti] + ibase + t;
      #pragma unroll
      for (int j=0;j<8;j++){
        float acc = S.pbv[j];
        #pragma unroll
        for (int ch=0;ch<8;ch++) acc += ln[ch]*S.pwm[j*8+ch];
        out[base + j*c_plen[ti]] = acc;
      }
    }
  }
}

// ---------------- K6: whole m1 path, register-blocked scan -----------------
__global__ void __launch_bounds__(512)
k6_m1(const float* __restrict__ t5, const float* __restrict__ in_w,
      const float* __restrict__ conv_w, const float* __restrict__ conv_b,
      const float* __restrict__ xproj_w, const float* __restrict__ dt_w,
      const float* __restrict__ dt_b, const float* __restrict__ Alog,
      const float* __restrict__ Dv, const float* __restrict__ out_w,
      const float* __restrict__ ng, const float* __restrict__ nbv,
      const float* __restrict__ pw, const float* __restrict__ pb,
      const float* __restrict__ skipp, float* __restrict__ out){
  __shared__ float s_iw[1024];              // in_w (64,16)
  __shared__ float s_x[64][17];
  __shared__ float s_xi[64][33];            // xi, then delta
  __shared__ float s_xc[64][33];
  __shared__ __align__(16) float s_B[64][20];
  __shared__ __align__(16) float s_C[64][20];
  __shared__ float s_dt[64];
  __shared__ float s_y[64][33];
  int b = blockIdx.x, tid = threadIdx.x;
  for (int i=tid;i<1024;i+=512) s_iw[i]=in_w[i];
  for (int i=tid;i<1024;i+=512){
    int t=i>>4, c=i&15;
    s_x[t][c] = t5[b*3072 + (32+c)*64 + t];
  }
  __syncthreads();
  for (int i=tid;i<2048;i+=512){     // in-proj xi (rows 0..31 of in_w)
    int t=i>>5, j=i&31;
    float v=0.f;
    #pragma unroll
    for (int c=0;c<16;c++) v += s_x[t][c]*s_iw[j*16+c];
    s_xi[t][j]=v;
  }
  __syncthreads();
  for (int i=tid;i<2048;i+=512){     // conv + silu
    int t=i>>5, d=i&31;
    float acc = conv_b[d];
    #pragma unroll
    for (int k=0;k<4;k++){
      int tt = t-3+k;
      if (tt>=0) acc += conv_w[d*4+k]*s_xi[tt][d];
    }
    s_xc[t][d] = siluf(acc);
  }
  __syncthreads();
  for (int i=tid;i<64*33;i+=512){    // x-proj
    int t=i/33, j=i%33;
    float v=0.f;
    #pragma unroll
    for (int d=0;d<32;d++) v += s_xc[t][d]*xproj_w[j*32+d];
    if (j==0) s_dt[t]=v;
    else if (j<17) s_B[t][j-1]=v;
    else s_C[t][j-17]=v;
  }
  __syncthreads();
  for (int i=tid;i<2048;i+=512){     // delta (overwrites s_xi)
    int t=i>>5, d=i&31;
    s_xi[t][d] = softplusf(s_dt[t]*dt_w[d] + dt_b[d]);
  }
  __syncthreads();
  if (tid < 128){                    // scan: thread=(d,ng), h[4] in regs
    int d=tid>>2, ngi=tid&3;
    float4 al = *reinterpret_cast<const float4*>(&Alog[d*16 + 4*ngi]);
    const float L2E = 1.4426950408889634f;
    float ac0=-__expf(al.x)*L2E, ac1=-__expf(al.y)*L2E,
          ac2=-__expf(al.z)*L2E, ac3=-__expf(al.w)*L2E;
    float h0=0.f,h1=0.f,h2=0.f,h3=0.f;
    #pragma unroll 4
    for (int t=0;t<64;t++){
      float dl = s_xi[t][d];
      float du = dl*s_xc[t][d];
      float4 Bv = *reinterpret_cast<const float4*>(&s_B[t][4*ngi]);
      float4 Cv = *reinterpret_cast<const float4*>(&s_C[t][4*ngi]);
      float a0=exp2f(dl*ac0), a1=exp2f(dl*ac1),
            a2=exp2f(dl*ac2), a3=exp2f(dl*ac3);
      h0 = a0*h0 + du*Bv.x;
      h1 = a1*h1 + du*Bv.y;
      h2 = a2*h2 + du*Bv.z;
      h3 = a3*h3 + du*Bv.w;
      float pr = h0*Cv.x + h1*Cv.y + h2*Cv.z + h3*Cv.w;
      pr += __shfl_xor_sync(0xffffffffu, pr, 1);
      pr += __shfl_xor_sync(0xffffffffu, pr, 2);
      if (ngi==0) s_y[t][d]=pr;
    }
  }
  __syncthreads();
  if (tid<64){
    int t=tid;
    float skip = skipp[0];
    float yf[32];
    #pragma unroll
    for (int d=0;d<32;d++){
      float z=0.f;                   // recompute z from staged x + in_w
      #pragma unroll
      for (int c=0;c<16;c++) z += s_x[t][c]*s_iw[(32+d)*16+c];
      yf[d] = (s_y[t][d] + s_xc[t][d]*Dv[d]) * siluf(z);
    }
    float o[16]; float mu=0.f;
    #pragma unroll
    for (int ch=0;ch<16;ch++){
      float acc = skip * s_x[t][ch];
      #pragma unroll
      for (int d=0;d<32;d++) acc += yf[d]*out_w[ch*32+d];
      o[ch]=acc; mu+=acc;
    }
    mu *= (1.0f/16.0f);
    float var=0.f;
    #pragma unroll
    for (int ch=0;ch<16;ch++){ float dv=o[ch]-mu; var+=dv*dv; }
    var *= (1.0f/16.0f);
    float rs = rsqrtf(var+1e-5f);
    float ln[16];
    #pragma unroll
    for (int ch=0;ch<16;ch++) ln[ch] = (o[ch]-mu)*rs*ng[ch]+nbv[ch];
    #pragma unroll
    for (int j=0;j<16;j++){
      float acc = pb[j];
      #pragma unroll
      for (int ch=0;ch<16;ch++) acc += ln[ch]*pw[j*16+ch];
      out[1835008 + b*3072 + (32+j)*64 + t] = acc;
    }
  }
}

// ---------------- launch ----------------
extern "C" void kernel_launch(void* const* d_in, const int* in_sizes, int n_in,
                              void* d_out, int out_size){
  (void)in_sizes; (void)n_in; (void)out_size;
  const float* t1 = (const float*)d_in[0];
  const float* t2 = (const float*)d_in[1];
  const float* t3 = (const float*)d_in[2];
  const float* t4 = (const float*)d_in[3];
  const float* t5 = (const float*)d_in[4];
  float* out = (float*)d_out;

  k3_scanA<<<NB*TOTC, 256>>>(t1,t2,t3,t4,t5,
                             (const float*)d_in[5],(const float*)d_in[8],
                             (const float*)d_in[6],(const float*)d_in[7],
                             (const float*)d_in[9],(const float*)d_in[10],
                             (const float*)d_in[11]);
  k4_chunk<<<32, 256>>>();
  k5_scanC<<<NB*TOTC, 256>>>(t1,t2,t3,t4,t5,
                             (const float*)d_in[5],(const float*)d_in[8],
                             (const float*)d_in[6],(const float*)d_in[7],
                             (const float*)d_in[9],(const float*)d_in[10],
                             (const float*)d_in[11],
                             (const float*)d_in[13],(const float*)d_in[12],
                             (const float*)d_in[23],(const float*)d_in[24],
                             (const float*)d_in[25],(const float*)d_in[26],
                             (const float*)d_in[31], out);
  k6_m1   <<<NB, 512>>>(t5,(const float*)d_in[14],(const float*)d_in[15],
                        (const float*)d_in[16],(const float*)d_in[17],
                        (const float*)d_in[18],(const float*)d_in[19],
                        (const float*)d_in[20],(const float*)d_in[21],
                        (const float*)d_in[22],(const float*)d_in[27],
                        (const float*)d_in[28],(const float*)d_in[29],
                        (const float*)d_in[30],(const float*)d_in[31], out);
}